// round 16
// baseline (speedup 1.0000x reference)
#include <cuda_runtime.h>
#include <cuda_bf16.h>
#include <cstdint>

#define KNN 16
#define NPTS 8192
#define DIMS 64
#define BLK 128
#define NBLK 64
#define NTHR 256
#define PITCH 144                  // bytes/row: 64 bf16 (128B) + 16B pad -> ldmatrix conflict-free
#define TERM_B (BLK * PITCH)       // 18432 per term image
#define IMG3_B (3 * TERM_B)        // 55296 per 128-point block

__device__ __align__(16) unsigned char g_img[2][NBLK][IMG3_B];
__device__ float g_nrm[2][NPTS];

// smem layout (bytes)
#define SM_A    0
#define SM_B0   IMG3_B                       // 55296
#define SM_B1   (SM_B0 + IMG3_B)             // 110592
#define SM_SAN  (SM_B1 + IMG3_B)             // 165888 (128 f32)
#define SM_STL  (SM_SAN + 512)               // 166400 (2 x 128 f32)
#define SM_KDS  (SM_STL + 1024)              // 167424 (512 lists x 16 f32)
#define SM_KIS  (SM_KDS + BLK * 4 * KNN * 4) // 200192 (u16)
#define SM_TOT  (SM_KIS + BLK * 4 * KNN * 2) // 216576

#define CP_ASYNC16(dst_u32, gptr) \
    asm volatile("cp.async.ca.shared.global [%0], [%1], 16;" :: "r"(dst_u32), "l"(gptr))
#define CP_COMMIT()  asm volatile("cp.async.commit_group;")
#define CP_WAIT0()   asm volatile("cp.async.wait_group 0;" ::: "memory")

#define LDM4(r0, r1, r2, r3, addr) \
    asm volatile("ldmatrix.sync.aligned.m8n8.x4.shared.b16 {%0,%1,%2,%3}, [%4];" \
        : "=r"(r0), "=r"(r1), "=r"(r2), "=r"(r3) : "r"(addr))

#define MMA(c, a0, a1, a2, a3, b0, b1) \
    asm volatile("mma.sync.aligned.m16n8k16.row.col.f32.bf16.bf16.f32 " \
        "{%0,%1,%2,%3}, {%4,%5,%6,%7}, {%8,%9}, {%0,%1,%2,%3};" \
        : "+f"((c)[0]), "+f"((c)[1]), "+f"((c)[2]), "+f"((c)[3]) \
        : "r"(a0), "r"(a1), "r"(a2), "r"(a3), "r"(b0), "r"(b1))

static __device__ __forceinline__ uint32_t s2u(const void* p) {
    uint32_t a;
    asm("{ .reg .u64 t; cvta.to.shared.u64 t, %1; cvt.u32.u64 %0, t; }" : "=r"(a) : "l"(p));
    return a;
}

// ---- pre-kernel: bf16 3-term split into padded row images + norms ----
__global__ __launch_bounds__(NTHR, 1)
void pre_kernel(const float* __restrict__ x) {
    const int b = blockIdx.y, blk = blockIdx.x, tid = threadIdx.x;
    const float* xb = x + ((size_t)b * NPTS + (size_t)blk * BLK) * DIMS;

    if (tid < BLK) {
        float s = 0.f;
        const float* p = xb + (size_t)tid * DIMS;
        #pragma unroll
        for (int d = 0; d < DIMS; d++) s = fmaf(p[d], p[d], s);
        g_nrm[b][blk * BLK + tid] = s;
    }
    unsigned char* img = g_img[b][blk];
    for (int i = tid; i < BLK * DIMS; i += NTHR) {
        const int row = i >> 6, col = i & 63;
        const float v = xb[row * DIMS + col];
        __nv_bfloat16 t0 = __float2bfloat16(v);
        float r1 = v - __bfloat162float(t0);
        __nv_bfloat16 t1 = __float2bfloat16(r1);
        float r2 = r1 - __bfloat162float(t1);
        __nv_bfloat16 t2 = __float2bfloat16(r2);
        const unsigned off = (unsigned)(row * PITCH + col * 2);
        *(__nv_bfloat16*)(img + 0 * TERM_B + off) = t0;
        *(__nv_bfloat16*)(img + 1 * TERM_B + off) = t1;
        *(__nv_bfloat16*)(img + 2 * TERM_B + off) = t2;
    }
}

// ---- main: bf16x3 mma.sync GEMM + private-list selection ----
__global__ __launch_bounds__(NTHR, 1)
void knn_mma(const float* __restrict__ x, float* __restrict__ out) {
    extern __shared__ __align__(16) unsigned char smem[];
    const uint32_t sb0 = s2u(smem);
    float* sanrm = (float*)(smem + SM_SAN);
    float* stile = (float*)(smem + SM_STL);
    float* kds   = (float*)(smem + SM_KDS);
    unsigned short* kis = (unsigned short*)(smem + SM_KIS);

    const int tid  = threadIdx.x;
    const int lane = tid & 31;
    const int warp = tid >> 5;        // 0..7 -> rows 16w..16w+15
    const int r    = lane >> 2;       // 0..7
    const int q    = lane & 3;        // 0..3
    const int batch = blockIdx.y;
    const int row0  = blockIdx.x * BLK;

    const float INF = __int_as_float(0x7f800000);

    // init lists
    for (int i = tid; i < BLK * 4 * KNN; i += NTHR) { kds[i] = INF; kis[i] = 0; }

    // stage A image + B(0)
    {
        const unsigned char* gA = g_img[batch][blockIdx.x];
        const unsigned char* gB = g_img[batch][0];
        for (int i = tid; i < IMG3_B / 16; i += NTHR) {
            CP_ASYNC16(sb0 + SM_A  + 16 * i, gA + 16 * i);
            CP_ASYNC16(sb0 + SM_B0 + 16 * i, gB + 16 * i);
        }
        CP_COMMIT();
    }
    if (tid < BLK) sanrm[tid] = g_nrm[batch][row0 + tid];

    CP_WAIT0();
    __syncthreads();

    const float sa0 = sanrm[16 * warp + r];
    const float sa1 = sanrm[16 * warp + r + 8];
    const int L0 = ((16 * warp + r) * 4 + q) * KNN;
    const int L1 = ((16 * warp + r + 8) * 4 + q) * KNN;
    float kth0 = INF, kth1 = INF;

    // ldmatrix lane address components
    const uint32_t a_base = sb0 + SM_A + (16 * warp + (lane & 15)) * PITCH
                          + ((lane & 16) ? 16u : 0u);
    const uint32_t b_lane = (lane & 7) * PITCH + ((lane & 16) ? 8u * PITCH : 0u)
                          + ((lane & 8) ? 16u : 0u);

    for (int t = 0; t < NBLK; t++) {
        CP_WAIT0();          // B(t) landed
        if (tid < BLK) stile[(t & 1) * BLK + tid] = g_nrm[batch][t * BLK + tid];
        __syncthreads();     // B(t)+stile visible; prev tile fully consumed

        if (t + 1 < NBLK) {  // prefetch B(t+1), overlaps compute
            const unsigned char* gB = g_img[batch][t + 1];
            const uint32_t dst = sb0 + ((t & 1) ? SM_B0 : SM_B1);
            for (int i = tid; i < IMG3_B / 16; i += NTHR)
                CP_ASYNC16(dst + 16 * i, gB + 16 * i);
            CP_COMMIT();
        }

        const uint32_t bB = sb0 + ((t & 1) ? SM_B1 : SM_B0) + b_lane;

        float acc[16][4];
        #pragma unroll
        for (int n = 0; n < 16; n++)
            #pragma unroll
            for (int e = 0; e < 4; e++) acc[n][e] = 0.f;

        #pragma unroll
        for (int ks = 0; ks < 4; ks++) {
            const uint32_t kofs = ks * 32;
            uint32_t bf[16][2];
            uint32_t a0, a1, a2, a3;

            // ---- B term 0: A terms 0,1,2 ----
            #pragma unroll
            for (int j = 0; j < 8; j++)
                LDM4(bf[2 * j][0], bf[2 * j][1], bf[2 * j + 1][0], bf[2 * j + 1][1],
                     bB + 0 * TERM_B + (16 * j) * PITCH + kofs);
            LDM4(a0, a1, a2, a3, a_base + 0 * TERM_B + kofs);
            #pragma unroll
            for (int n = 0; n < 16; n++) MMA(acc[n], a0, a1, a2, a3, bf[n][0], bf[n][1]);
            LDM4(a0, a1, a2, a3, a_base + 1 * TERM_B + kofs);
            #pragma unroll
            for (int n = 0; n < 16; n++) MMA(acc[n], a0, a1, a2, a3, bf[n][0], bf[n][1]);
            LDM4(a0, a1, a2, a3, a_base + 2 * TERM_B + kofs);
            #pragma unroll
            for (int n = 0; n < 16; n++) MMA(acc[n], a0, a1, a2, a3, bf[n][0], bf[n][1]);

            // ---- B term 1: A terms 0,1 ----
            #pragma unroll
            for (int j = 0; j < 8; j++)
                LDM4(bf[2 * j][0], bf[2 * j][1], bf[2 * j + 1][0], bf[2 * j + 1][1],
                     bB + 1 * TERM_B + (16 * j) * PITCH + kofs);
            LDM4(a0, a1, a2, a3, a_base + 0 * TERM_B + kofs);
            #pragma unroll
            for (int n = 0; n < 16; n++) MMA(acc[n], a0, a1, a2, a3, bf[n][0], bf[n][1]);
            LDM4(a0, a1, a2, a3, a_base + 1 * TERM_B + kofs);
            #pragma unroll
            for (int n = 0; n < 16; n++) MMA(acc[n], a0, a1, a2, a3, bf[n][0], bf[n][1]);

            // ---- B term 2: A term 0 ----
            #pragma unroll
            for (int j = 0; j < 8; j++)
                LDM4(bf[2 * j][0], bf[2 * j][1], bf[2 * j + 1][0], bf[2 * j + 1][1],
                     bB + 2 * TERM_B + (16 * j) * PITCH + kofs);
            LDM4(a0, a1, a2, a3, a_base + 0 * TERM_B + kofs);
            #pragma unroll
            for (int n = 0; n < 16; n++) MMA(acc[n], a0, a1, a2, a3, bf[n][0], bf[n][1]);
        }

        // ---- selection from accumulators (ascending col -> stable) ----
        const float* stl = &stile[(t & 1) * BLK];
        #pragma unroll
        for (int n = 0; n < 16; n++) {
            #pragma unroll
            for (int e = 0; e < 2; e++) {
                const int col = 8 * n + 2 * q + e;
                const float sbv = stl[col];
                const float d0 = (sa0 - 2.f * acc[n][e])     + sbv;
                const float d1 = (sa1 - 2.f * acc[n][2 + e]) + sbv;
                const unsigned short gcol = (unsigned short)(t * BLK + col);
                if (d0 < kth0) {
                    int j = KNN - 1;
                    while (j > 0 && kds[L0 + j - 1] > d0) {
                        kds[L0 + j] = kds[L0 + j - 1];
                        kis[L0 + j] = kis[L0 + j - 1];
                        j--;
                    }
                    kds[L0 + j] = d0; kis[L0 + j] = gcol;
                    kth0 = kds[L0 + KNN - 1];
                }
                if (d1 < kth1) {
                    int j = KNN - 1;
                    while (j > 0 && kds[L1 + j - 1] > d1) {
                        kds[L1 + j] = kds[L1 + j - 1];
                        kis[L1 + j] = kis[L1 + j - 1];
                        j--;
                    }
                    kds[L1 + j] = d1; kis[L1 + j] = gcol;
                    kth1 = kds[L1 + KNN - 1];
                }
            }
        }
        // loop-top barrier separates selection(t) from buffer reuse
    }

    __syncthreads();

    // ---- merge 4 sorted sub-lists per row (lexicographic); write output ----
    if (tid < BLK) {
        float* out_nn = out;
        float* out_c  = out + 2 * NPTS * KNN;
        const int grow = row0 + tid;
        const size_t obase = ((size_t)batch * NPTS + grow) * KNN;

        int ptr4[4] = {0, 0, 0, 0};
        #pragma unroll
        for (int j = 0; j < KNN; j++) {
            float best = INF; int bidx = 0x7fffffff; int bl = 0;
            #pragma unroll
            for (int l = 0; l < 4; l++) {
                if (ptr4[l] < KNN) {
                    const int bs = (tid * 4 + l) * KNN + ptr4[l];
                    const float dv = kds[bs];
                    const int   iv = (int)kis[bs];
                    if (dv < best || (dv == best && iv < bidx)) {
                        best = dv; bidx = iv; bl = l;
                    }
                }
            }
            ptr4[bl]++;
            out_nn[obase + j] = (float)bidx;
            out_c [obase + j] = (float)grow;
        }
    }
}

extern "C" void kernel_launch(void* const* d_in, const int* in_sizes, int n_in,
                              void* d_out, int out_size) {
    const float* x = (const float*)d_in[0];
    float* out = (float*)d_out;

    cudaFuncSetAttribute(knn_mma,
                         cudaFuncAttributeMaxDynamicSharedMemorySize, SM_TOT);

    dim3 pgrid(NBLK, 2);
    pre_kernel<<<pgrid, NTHR>>>(x);

    dim3 grid(NBLK, 2);
    knn_mma<<<grid, NTHR, SM_TOT>>>(x, out);
}